// round 2
// baseline (speedup 1.0000x reference)
#include <cuda_runtime.h>

// Fully fused VQC evaluation.
//
// Math: the circuit is (per-sample RY encoding) followed by a sample-
// independent unitary U built from q_weights. <Z0> collapses to a trilinear
// form  z = sum_{p,q,r} C[p][q][r] * u0_p * u1_q * u2_r,
// u_i = (1, cos x_i, sin x_i), with 27 coefficients derived from
// A = Re(U^T Z0 U) (U is real-represented via separate re/im parts).
//
// Every block rebuilds the 27 coefficients (cheap: ~hundreds of flops on a
// few threads, hidden under the DRAM latency of the batched input loads),
// so the whole problem is ONE kernel launch.

static constexpr int SPT = 4;     // samples per thread
static constexpr int BLOCK = 256;

__global__ void __launch_bounds__(BLOCK) vqc_fused(const float4* __restrict__ in,
                                                   float* __restrict__ out,
                                                   const float* __restrict__ qw,
                                                   int B) {
    __shared__ float Ure[8][8];
    __shared__ float Uim[8][8];
    __shared__ float A[8][8];
    __shared__ float cc_sh[27];

    const int t = threadIdx.x;
    const int T = gridDim.x * BLOCK;
    const int g = blockIdx.x * BLOCK + t;

    // ---- Issue all input loads FIRST (independent of coefficients) --------
    int idx[SPT];
    float4 x[SPT];
    #pragma unroll
    for (int k = 0; k < SPT; k++) {
        int i = g + k * T;
        idx[k] = i;
        int ii = (i < B) ? i : (B - 1);     // clamp: load always, store guarded
        x[k] = in[(size_t)ii * 2];          // first 16B of the 32B row
    }

    // ---- Per-block coefficient build (overlaps with loads in flight) ------
    if (t < 8) {
        const int j = t;
        float sr[8], si[8];
        #pragma unroll
        for (int m = 0; m < 8; m++) { sr[m] = 0.f; si[m] = 0.f; }
        sr[j] = 1.0f;

        for (int l = 0; l < 3; l++) {
            #pragma unroll
            for (int q = 0; q < 3; q++) {
                float ty = qw[(l * 3 + q) * 2 + 0];
                float tz = qw[(l * 3 + q) * 2 + 1];
                int bit = 4 >> q;

                float c, s;
                __sincosf(0.5f * ty, &s, &c);
                #pragma unroll
                for (int m = 0; m < 8; m++) {
                    if (m & bit) continue;
                    int m1 = m | bit;
                    float ar = sr[m],  ai = si[m];
                    float br = sr[m1], bi = si[m1];
                    sr[m]  = c * ar - s * br;  si[m]  = c * ai - s * bi;
                    sr[m1] = s * ar + c * br;  si[m1] = s * ai + c * bi;
                }

                float cz, sz;
                __sincosf(0.5f * tz, &sz, &cz);
                #pragma unroll
                for (int m = 0; m < 8; m++) {
                    float ar = sr[m], ai = si[m];
                    if (m & bit) { sr[m] = cz * ar - sz * ai; si[m] = cz * ai + sz * ar; }
                    else         { sr[m] = cz * ar + sz * ai; si[m] = cz * ai - sz * ar; }
                }
            }
            // CNOT01: swap (4,6),(5,7)
            #pragma unroll
            for (int m = 4; m < 6; m++) {
                int m1 = m | 2; float tmp;
                tmp = sr[m]; sr[m] = sr[m1]; sr[m1] = tmp;
                tmp = si[m]; si[m] = si[m1]; si[m1] = tmp;
            }
            // CNOT12: swap (2,3),(6,7)
            #pragma unroll
            for (int m = 2; m < 8; m += 4) {
                int m1 = m | 1; float tmp;
                tmp = sr[m]; sr[m] = sr[m1]; sr[m1] = tmp;
                tmp = si[m]; si[m] = si[m1]; si[m1] = tmp;
            }
        }
        #pragma unroll
        for (int m = 0; m < 8; m++) { Ure[m][j] = sr[m]; Uim[m][j] = si[m]; }
    }
    __syncthreads();

    if (t < 64) {
        int j = t >> 3, k = t & 7;
        float a = 0.f;
        #pragma unroll
        for (int m = 0; m < 8; m++) {
            float sgn = (m & 4) ? -1.f : 1.f;
            a += sgn * (Ure[m][j] * Ure[m][k] + Uim[m][j] * Uim[m][k]);
        }
        A[j][k] = a;
    }
    __syncthreads();

    if (t < 27) {
        int p = t / 9, q = (t / 3) % 3, r = t % 3;
        float csum = 0.f;
        for (int j = 0; j < 8; j++) {
            for (int k = 0; k < 8; k++) {
                int a0 = (j >> 2) & 1, b0 = (k >> 2) & 1;
                int a1 = (j >> 1) & 1, b1 = (k >> 1) & 1;
                int a2 = j & 1,        b2 = k & 1;
                float g0 = (a0 == b0) ? ((p == 0) ? 0.5f : (p == 1) ? (a0 ? -0.5f : 0.5f) : 0.f)
                                      : ((p == 2) ? 0.5f : 0.f);
                float g1 = (a1 == b1) ? ((q == 0) ? 0.5f : (q == 1) ? (a1 ? -0.5f : 0.5f) : 0.f)
                                      : ((q == 2) ? 0.5f : 0.f);
                float g2 = (a2 == b2) ? ((r == 0) ? 0.5f : (r == 1) ? (a2 ? -0.5f : 0.5f) : 0.f)
                                      : ((r == 2) ? 0.5f : 0.f);
                csum += A[j][k] * g0 * g1 * g2;
            }
        }
        cc_sh[t] = csum;
    }
    __syncthreads();

    // ---- Pull coefficients into registers (broadcast LDS, conflict-free) --
    float cc[27];
    #pragma unroll
    for (int i = 0; i < 27; i++) cc[i] = cc_sh[i];

    // ---- Evaluate SPT samples ---------------------------------------------
    #pragma unroll
    for (int k = 0; k < SPT; k++) {
        float C0, S0, C1, S1, C2, S2;
        __sincosf(x[k].x, &S0, &C0);
        __sincosf(x[k].y, &S1, &C1);
        __sincosf(x[k].z, &S2, &C2);

        float u0[3] = {1.f, C0, S0};
        float u1[3] = {1.f, C1, S1};
        float z = 0.f;
        #pragma unroll
        for (int p = 0; p < 3; p++) {
            #pragma unroll
            for (int q = 0; q < 3; q++) {
                const float* c3 = &cc[p * 9 + q * 3];
                float w = c3[0];
                w = fmaf(c3[1], C2, w);
                w = fmaf(c3[2], S2, w);
                z = fmaf(u0[p] * u1[q], w, z);
            }
        }
        if (idx[k] < B) out[idx[k]] = z;
    }
}

extern "C" void kernel_launch(void* const* d_in, const int* in_sizes, int n_in,
                              void* d_out, int out_size) {
    const float* inputs = (const float*)d_in[0];   // (B, 8) float32
    const float* qw     = (const float*)d_in[1];   // (3, 3, 2) float32
    float* out          = (float*)d_out;           // (B, 1) float32

    int B = in_sizes[0] / 8;
    int grid = (B + BLOCK * SPT - 1) / (BLOCK * SPT);
    vqc_fused<<<grid, BLOCK>>>((const float4*)inputs, out, qw, B);
}

// round 3
// speedup vs baseline: 1.0667x; 1.0667x over previous
#include <cuda_runtime.h>

// z = sum_{p,q,r} C[p*9+q*3+r] * u0_p * u1_q * u2_r,  u_i = (1, cos x_i, sin x_i)
__device__ float d_C[27];

// ---------------------------------------------------------------------------
// Kernel 1: build the 27 trilinear coefficients from q_weights (18 floats).
// One block, 64 threads.
// ---------------------------------------------------------------------------
__global__ void build_coeffs(const float* __restrict__ qw) {
    __shared__ float Ure[8][8];
    __shared__ float Uim[8][8];
    __shared__ float A[8][8];

    int t = threadIdx.x;

    if (t < 8) {
        const int j = t;
        float sr[8], si[8];
        #pragma unroll
        for (int m = 0; m < 8; m++) { sr[m] = 0.f; si[m] = 0.f; }
        sr[j] = 1.0f;

        for (int l = 0; l < 3; l++) {
            #pragma unroll
            for (int q = 0; q < 3; q++) {
                float ty = qw[(l * 3 + q) * 2 + 0];
                float tz = qw[(l * 3 + q) * 2 + 1];
                int bit = 4 >> q;

                float c, s;
                __sincosf(0.5f * ty, &s, &c);
                #pragma unroll
                for (int m = 0; m < 8; m++) {
                    if (m & bit) continue;
                    int m1 = m | bit;
                    float ar = sr[m],  ai = si[m];
                    float br = sr[m1], bi = si[m1];
                    sr[m]  = c * ar - s * br;  si[m]  = c * ai - s * bi;
                    sr[m1] = s * ar + c * br;  si[m1] = s * ai + c * bi;
                }

                float cz, sz;
                __sincosf(0.5f * tz, &sz, &cz);
                #pragma unroll
                for (int m = 0; m < 8; m++) {
                    float ar = sr[m], ai = si[m];
                    if (m & bit) { sr[m] = cz * ar - sz * ai; si[m] = cz * ai + sz * ar; }
                    else         { sr[m] = cz * ar + sz * ai; si[m] = cz * ai - sz * ar; }
                }
            }
            // CNOT01: swap (4,6),(5,7)
            #pragma unroll
            for (int m = 4; m < 6; m++) {
                int m1 = m | 2; float tmp;
                tmp = sr[m]; sr[m] = sr[m1]; sr[m1] = tmp;
                tmp = si[m]; si[m] = si[m1]; si[m1] = tmp;
            }
            // CNOT12: swap (2,3),(6,7)
            #pragma unroll
            for (int m = 2; m < 8; m += 4) {
                int m1 = m | 1; float tmp;
                tmp = sr[m]; sr[m] = sr[m1]; sr[m1] = tmp;
                tmp = si[m]; si[m] = si[m1]; si[m1] = tmp;
            }
        }
        #pragma unroll
        for (int m = 0; m < 8; m++) { Ure[m][j] = sr[m]; Uim[m][j] = si[m]; }
    }
    __syncthreads();

    if (t < 64) {
        int j = t >> 3, k = t & 7;
        float a = 0.f;
        #pragma unroll
        for (int m = 0; m < 8; m++) {
            float sgn = (m & 4) ? -1.f : 1.f;
            a += sgn * (Ure[m][j] * Ure[m][k] + Uim[m][j] * Uim[m][k]);
        }
        A[j][k] = a;
    }
    __syncthreads();

    if (t < 27) {
        int p = t / 9, q = (t / 3) % 3, r = t % 3;
        float csum = 0.f;
        for (int j = 0; j < 8; j++) {
            for (int k = 0; k < 8; k++) {
                int a0 = (j >> 2) & 1, b0 = (k >> 2) & 1;
                int a1 = (j >> 1) & 1, b1 = (k >> 1) & 1;
                int a2 = j & 1,        b2 = k & 1;
                float g0 = (a0 == b0) ? ((p == 0) ? 0.5f : (p == 1) ? (a0 ? -0.5f : 0.5f) : 0.f)
                                      : ((p == 2) ? 0.5f : 0.f);
                float g1 = (a1 == b1) ? ((q == 0) ? 0.5f : (q == 1) ? (a1 ? -0.5f : 0.5f) : 0.f)
                                      : ((q == 2) ? 0.5f : 0.f);
                float g2 = (a2 == b2) ? ((r == 0) ? 0.5f : (r == 1) ? (a2 ? -0.5f : 0.5f) : 0.f)
                                      : ((r == 2) ? 0.5f : 0.f);
                csum += A[j][k] * g0 * g1 * g2;
            }
        }
        d_C[t] = csum;
    }
}

// ---------------------------------------------------------------------------
// Kernel 2: evaluate. MLP-maximized: 8 unconditional LDG.128 front-batched
// per thread, coefficients via shared (single cheap barrier), guarded stores.
// ---------------------------------------------------------------------------
static constexpr int SPT = 8;     // samples per thread
static constexpr int BLOCK = 256;

__global__ void __launch_bounds__(BLOCK) vqc_eval(const float4* __restrict__ in,
                                                  float* __restrict__ out, int B) {
    __shared__ float cs[27];
    if (threadIdx.x < 27) cs[threadIdx.x] = d_C[threadIdx.x];

    const int T = gridDim.x * BLOCK;
    const int t = blockIdx.x * BLOCK + threadIdx.x;

    // Front-batch ALL loads (clamped, unconditional) -> MLP_p1 = 8
    float4 x[SPT];
    #pragma unroll
    for (int k = 0; k < SPT; k++) {
        int i = t + k * T;
        i = (i < B) ? i : (B - 1);
        x[k] = in[(size_t)i * 2];     // first 16B of the 32B row (x0..x3)
    }
    __syncthreads();   // cs ready; arrives while loads are in flight

    #pragma unroll
    for (int k = 0; k < SPT; k++) {
        float C0, S0, C1, S1, C2, S2;
        __sincosf(x[k].x, &S0, &C0);
        __sincosf(x[k].y, &S1, &C1);
        __sincosf(x[k].z, &S2, &C2);

        float u0[3] = {1.f, C0, S0};
        float u1[3] = {1.f, C1, S1};
        float z = 0.f;
        #pragma unroll
        for (int p = 0; p < 3; p++) {
            #pragma unroll
            for (int q = 0; q < 3; q++) {
                const float* c3 = &cs[p * 9 + q * 3];
                float w = c3[0];
                w = fmaf(c3[1], C2, w);
                w = fmaf(c3[2], S2, w);
                z = fmaf(u0[p] * u1[q], w, z);
            }
        }
        int i = t + k * T;
        if (i < B) out[i] = z;
    }
}

extern "C" void kernel_launch(void* const* d_in, const int* in_sizes, int n_in,
                              void* d_out, int out_size) {
    const float* inputs = (const float*)d_in[0];   // (B, 8) float32
    const float* qw     = (const float*)d_in[1];   // (3, 3, 2) float32
    float* out          = (float*)d_out;           // (B, 1) float32

    int B = in_sizes[0] / 8;

    build_coeffs<<<1, 64>>>(qw);

    int grid = (B + BLOCK * SPT - 1) / (BLOCK * SPT);   // 512 for B = 2^20
    vqc_eval<<<grid, BLOCK>>>((const float4*)inputs, out, B);
}